// round 6
// baseline (speedup 1.0000x reference)
#include <cuda_runtime.h>

#define DI 1024
#define D2 2048
#define BB 32
#define SS 128
#define KK 512
#define NSTEP 12
#define NBLK 148
#define NTHR 256

// ---------------- static device scratch ----------------
__device__ __align__(16) float g_qpa[NSTEP * BB * DI];        // [s][b][d]
__device__ __align__(16) float g_qpaP[2 * BB * NSTEP * DI];   // P0a partials (z=2)
__device__ __align__(16) float g_cq2P[2 * NSTEP * BB * DI];   // P0c partials (z=2)
__device__ __align__(16) float g_cq2[NSTEP * BB * DI];        // [s][b][d]
__device__ __align__(16) float g_riwT[D2 * DI];               // riwT[j'][i]
__device__ __align__(16) float g_control[BB * DI];
__device__ __align__(16) float g_mem[BB * DI];
__device__ __align__(16) float g_v[BB * DI];
__device__ __align__(16) float g_read[BB * DI];
__device__ __align__(16) float g_clog[BB * SS];
__device__ __align__(16) float g_rlog[BB * KK];
__device__ __align__(16) float g_partA[4 * BB * DI];          // cq partials
__device__ __align__(16) float g_partB[4 * BB * DI];          // mem_p partials
__device__ __align__(16) float g_partU[4 * BB * D2];          // u partials
__device__ __align__(16) float g_partW[8 * BB * DI];          // new_memory partials
__device__ unsigned g_count = 0;
__device__ unsigned g_gen = 0;

// ---------------- grid-wide barrier ----------------
__device__ __forceinline__ void gsync() {
    __syncthreads();
    if (threadIdx.x == 0) {
        __threadfence();
        unsigned gen = *(volatile unsigned*)&g_gen;
        if (atomicAdd(&g_count, 1u) == NBLK - 1) {
            atomicExch(&g_count, 0u);
            __threadfence();
            atomicAdd(&g_gen, 1u);
        } else {
            while (*(volatile unsigned*)&g_gen == gen) __nanosleep(64);
        }
        __threadfence();
    }
    __syncthreads();
}

// ---------------- 64m x 32n GEMM tile over one k-chunk ----------------
// dst[n*dstride + m0+m] = sum_{k in [kbase,kbase+kchunk)} A[m0+m][k] * act[n][kact + (k-kbase)]
__device__ __forceinline__ void gemm_tile(
    const float* __restrict__ A, int lda, int m0, int kbase, int kchunk,
    const float* __restrict__ act, int ldact, int kact,
    float* __restrict__ dst, int dstride, const float* __restrict__ bias,
    float* __restrict__ pool) {
    float* As = pool;          // [64][65]
    float* Bs = pool + 4160;   // [64][36]
    const int tid = threadIdx.x;
    const int tm = tid & 31;
    const int n0 = (tid >> 5) * 4;
    float acc[2][4] = {};
    for (int ks = 0; ks < kchunk; ks += 64) {
#pragma unroll
        for (int i = 0; i < 4; i++) {
            int idx = tid + 256 * i;
            int kg = idx & 15, m = idx >> 4;
            float4 av = *(const float4*)(A + (size_t)(m0 + m) * lda + kbase + ks + kg * 4);
            float* as = As + m * 65 + kg * 4;
            as[0] = av.x; as[1] = av.y; as[2] = av.z; as[3] = av.w;
        }
#pragma unroll
        for (int i = 0; i < 2; i++) {
            int n = (tid & 15) + 16 * i;
            int kg = tid >> 4;
            float4 bv = *(const float4*)(act + (size_t)n * ldact + kact + ks + kg * 4);
            Bs[(kg * 4 + 0) * 36 + n] = bv.x;
            Bs[(kg * 4 + 1) * 36 + n] = bv.y;
            Bs[(kg * 4 + 2) * 36 + n] = bv.z;
            Bs[(kg * 4 + 3) * 36 + n] = bv.w;
        }
        __syncthreads();
#pragma unroll
        for (int k = 0; k < 64; k++) {
            float4 bv = *(const float4*)(Bs + k * 36 + n0);
            float a0 = As[tm * 65 + k], a1 = As[(tm + 32) * 65 + k];
            acc[0][0] += a0 * bv.x; acc[0][1] += a0 * bv.y;
            acc[0][2] += a0 * bv.z; acc[0][3] += a0 * bv.w;
            acc[1][0] += a1 * bv.x; acc[1][1] += a1 * bv.y;
            acc[1][2] += a1 * bv.z; acc[1][3] += a1 * bv.w;
        }
        __syncthreads();
    }
#pragma unroll
    for (int r = 0; r < 2; r++) {
        int m = m0 + tm + 32 * r;
        float bs = bias ? bias[m] : 0.0f;
#pragma unroll
        for (int c = 0; c < 4; c++)
            dst[(size_t)(n0 + c) * dstride + m] = acc[r][c] + bs;
    }
}

// ---------------- one persistent kernel ----------------
__global__ void __launch_bounds__(NTHR) mac_persistent(
    const float* __restrict__ ctx, const float* __restrict__ question,
    const float* __restrict__ kn, const float* __restrict__ cinit,
    const float* __restrict__ pa_w, const float* __restrict__ pa_b,
    const float* __restrict__ cq_w, const float* __restrict__ cq_b,
    const float* __restrict__ caw, const float* __restrict__ rm_w,
    const float* __restrict__ rm_b, const float* __restrict__ ri_w,
    const float* __restrict__ raw, const float* __restrict__ wm_w,
    const float* __restrict__ wm_b, float* __restrict__ out) {
    __shared__ __align__(16) float pool[6464];  // 25.9 KB
    const int bid = blockIdx.x;
    const int tid = threadIdx.x;

    // ===== P0a: qpa partial GEMM (384 tasks) + ri_w transpose + control init =====
    for (int t = bid; t < 384; t += NBLK) {
        int mt = t % 192, z = t / 192;
        gemm_tile(pa_w, D2, mt * 64, z * 1024, 1024, question, D2, z * 1024,
                  g_qpaP + (size_t)z * BB * (NSTEP * DI), NSTEP * DI, nullptr, pool);
    }
    {
        int tx = tid & 31, ty = tid >> 5;  // ty 0..7
        for (int t = bid; t < 2048; t += NBLK) {
            int jt = t & 63, it = t >> 6;
            int j0 = jt * 32, i0 = it * 32;
            __syncthreads();
#pragma unroll
            for (int r = 0; r < 32; r += 8)
                pool[(ty + r) * 33 + tx] = ri_w[(size_t)(i0 + ty + r) * D2 + j0 + tx];
            __syncthreads();
#pragma unroll
            for (int r = 0; r < 32; r += 8)
                g_riwT[(size_t)(j0 + ty + r) * DI + i0 + tx] = pool[tx * 33 + ty + r];
        }
    }
    for (int i = bid * NTHR + tid; i < BB * DI; i += NBLK * NTHR) g_control[i] = cinit[0];
    gsync();

    // ===== P0b: reduce qpa partials (+bias, scatter to [s][b][d], memory0) =====
    for (int idx = bid * NTHR + tid; idx < BB * NSTEP * DI; idx += NBLK * NTHR) {
        int n = idx / (NSTEP * DI);
        int m = idx - n * (NSTEP * DI);
        float v = pa_b[m] + g_qpaP[(size_t)n * (NSTEP * DI) + m]
                          + g_qpaP[(size_t)(BB + n) * (NSTEP * DI) + m];
        int s0 = m >> 10, d = m & 1023;
        g_qpa[(size_t)(s0 * BB + n) * DI + d] = v;
        if (s0 == 0) g_mem[n * DI + d] = v;
    }
    gsync();

    // ===== P0c: cq2 partials (384 tasks: 12 s x 16 m x 2 z) =====
    for (int t = bid; t < 384; t += NBLK) {
        int nb = t % 12, mt = (t / 12) & 15, z = t / 192;
        gemm_tile(cq_w + DI, D2, mt * 64, z * 512, 512,
                  g_qpa + (size_t)nb * BB * DI, DI, z * 512,
                  g_cq2P + (size_t)(z * NSTEP + nb) * BB * DI, DI, nullptr, pool);
    }
    gsync();

    // ===== P0d: reduce cq2 partials + bias =====
    for (int idx = bid * NTHR + tid; idx < NSTEP * BB * DI; idx += NBLK * NTHR) {
        int d = idx & 1023;
        g_cq2[idx] = cq_b[d] + g_cq2P[idx] + g_cq2P[(size_t)NSTEP * BB * DI + idx];
    }
    gsync();

    // ===== 12 recurrent steps =====
    for (int s = 0; s < NSTEP; s++) {
        // ---- P1: cq control-half + mem_p split-k partials (128 tasks) ----
        if (bid < 128) {
            if (bid < 64) {
                int mt = bid & 15, z = bid >> 4;
                gemm_tile(cq_w, D2, mt * 64, z * 256, 256, g_control, DI, z * 256,
                          g_partA + (size_t)z * BB * DI, DI, nullptr, pool);
            } else {
                int q = bid - 64;
                int mt = q & 15, z = q >> 4;
                gemm_tile(rm_w, DI, mt * 64, z * 256, 256, g_mem, DI, z * 256,
                          g_partB + (size_t)z * BB * DI, DI, nullptr, pool);
            }
        }
        gsync();

        // ---- P2: context logits (128 tasks: 32 b x 4 sc) ----
        if (bid < 128) {
            int b = bid >> 2, sc = bid & 3;
            float* w = pool;  // [1024]
            const float* cq2s = g_cq2 + ((size_t)s * BB + b) * DI;
            for (int d = tid; d < DI; d += NTHR) {
                float v = cq2s[d];
#pragma unroll
                for (int z = 0; z < 4; z++) v += g_partA[(size_t)(z * BB + b) * DI + d];
                w[d] = v * caw[d];
            }
            __syncthreads();
            int warp = tid >> 5, lane = tid & 31;
            const float4* w4 = (const float4*)w;
#pragma unroll
            for (int ri = 0; ri < 4; ri++) {
                int srow = sc * 32 + warp * 4 + ri;
                const float4* crow = (const float4*)(ctx + (size_t)(b * SS + srow) * DI);
                float acc = 0.f;
#pragma unroll
                for (int t2 = 0; t2 < 8; t2++) {
                    float4 f = crow[lane + 32 * t2];
                    float4 g = w4[lane + 32 * t2];
                    acc += f.x * g.x + f.y * g.y + f.z * g.z + f.w * g.w;
                }
#pragma unroll
                for (int o = 16; o; o >>= 1) acc += __shfl_xor_sync(0xffffffffu, acc, o);
                if (lane == 0) g_clog[b * SS + srow] = acc;
            }
            __syncthreads();
        }
        gsync();

        // ---- P3: context softmax + weighted sum -> control, v (128 tasks) ----
        if (bid < 128) {
            int b = bid >> 2, dc = bid & 3;
            float* ps = pool;          // [128]
            float* red = pool + 128;   // [128]
            if (tid < SS) { float l = g_clog[b * SS + tid]; ps[tid] = l; red[tid] = l; }
            __syncthreads();
            for (int st = 64; st >= 1; st >>= 1) {
                if (tid < st) red[tid] = fmaxf(red[tid], red[tid + st]);
                __syncthreads();
            }
            float mx = red[0];
            __syncthreads();
            if (tid < SS) { float e = __expf(ps[tid] - mx); ps[tid] = e; red[tid] = e; }
            __syncthreads();
            for (int st = 64; st >= 1; st >>= 1) {
                if (tid < st) red[tid] += red[tid + st];
                __syncthreads();
            }
            float inv = 1.0f / red[0];
            __syncthreads();
            int d = dc * 256 + tid;
            const float* base = ctx + (size_t)b * SS * DI + d;
            float acc = 0.f;
#pragma unroll 16
            for (int s2 = 0; s2 < SS; s2++) acc += ps[s2] * base[(size_t)s2 * DI];
            acc *= inv;
            g_control[b * DI + d] = acc;
            g_v[b * DI + d] = acc * raw[d];
            __syncthreads();
        }
        gsync();

        // ---- P4: u = v @ riwT^T (128 tasks: 32 m x 4 z) ----
        if (bid < 128) {
            int mt = bid & 31, z = bid >> 5;
            gemm_tile(g_riwT, DI, mt * 64, z * 256, 256, g_v, DI, z * 256,
                      g_partU + (size_t)z * BB * D2, D2, nullptr, pool);
        }
        gsync();

        // ---- P5: knowledge logits (128 tasks: 32 b x 4 kc) ----
        if (bid < 128) {
            int b = bid >> 2, kc = bid & 3;
            float* w2 = pool;          // [1024]
            float* half = pool + 1024; // [128]
            for (int jj = tid; jj < DI; jj += NTHR) {
                float mp = rm_b[jj], u1 = 0.f, u2 = 0.f;
#pragma unroll
                for (int z = 0; z < 4; z++) {
                    mp += g_partB[(size_t)(z * BB + b) * DI + jj];
                    u1 += g_partU[(size_t)(z * BB + b) * D2 + jj];
                    u2 += g_partU[(size_t)(z * BB + b) * D2 + DI + jj];
                }
                w2[jj] = mp * u1 + u2;
            }
            __syncthreads();
            int k = kc * 128 + (tid & 127);
            int jh = tid >> 7;
            const float* base = kn + (size_t)b * DI * KK + (size_t)(jh * 512) * KK + k;
            const float* ww = w2 + jh * 512;
            float acc = 0.f;
#pragma unroll 8
            for (int j = 0; j < 512; j++) acc += ww[j] * base[(size_t)j * KK];
            if (jh) half[tid & 127] = acc;
            __syncthreads();
            if (!jh) g_rlog[b * KK + k] = acc + half[tid];
            __syncthreads();
        }
        gsync();

        // ---- P6: knowledge softmax + read (128 tasks: 32 b x 4 ic) ----
        if (bid < 128) {
            int b = bid >> 2, ic = bid & 3;
            float* ps = pool;          // [512]
            float* red = pool + 512;   // [256]
            float v0 = g_rlog[(size_t)b * KK + tid];
            float v1 = g_rlog[(size_t)b * KK + 256 + tid];
            red[tid] = fmaxf(v0, v1);
            __syncthreads();
            for (int st = 128; st >= 1; st >>= 1) {
                if (tid < st) red[tid] = fmaxf(red[tid], red[tid + st]);
                __syncthreads();
            }
            float mx = red[0];
            __syncthreads();
            float e0 = __expf(v0 - mx), e1 = __expf(v1 - mx);
            ps[tid] = e0;
            ps[tid + 256] = e1;
            red[tid] = e0 + e1;
            __syncthreads();
            for (int st = 128; st >= 1; st >>= 1) {
                if (tid < st) red[tid] += red[tid + st];
                __syncthreads();
            }
            float inv = 1.0f / red[0];
            __syncthreads();
            int warp = tid >> 5, lane = tid & 31;
            const float4* p4 = (const float4*)ps;
#pragma unroll
            for (int ii = 0; ii < 32; ii++) {
                int i = ic * 256 + warp * 32 + ii;
                const float4* row = (const float4*)(kn + (size_t)(b * DI + i) * KK);
                float acc = 0.f;
#pragma unroll
                for (int t2 = 0; t2 < 4; t2++) {
                    float4 f = row[lane + 32 * t2];
                    float4 q = p4[lane + 32 * t2];
                    acc += f.x * q.x + f.y * q.y + f.z * q.z + f.w * q.w;
                }
#pragma unroll
                for (int o = 16; o; o >>= 1) acc += __shfl_xor_sync(0xffffffffu, acc, o);
                if (lane == 0) g_read[b * DI + i] = acc * inv;
            }
            __syncthreads();
        }
        gsync();

        // ---- P7: new_memory partials (128 tasks: 16 m x 8 z) ----
        if (bid < 128) {
            int mt = bid & 15, z = bid >> 4;
            const float* act = (z < 4) ? g_read : g_mem;
            int kact = (z < 4) ? z * 256 : (z - 4) * 256;
            gemm_tile(wm_w, D2, mt * 64, z * 256, 256, act, DI, kact,
                      g_partW + (size_t)z * BB * DI, DI, nullptr, pool);
        }
        gsync();

        // ---- P8: reduce new_memory partials ----
        {
            int i = bid * NTHR + tid;
            if (i < BB * DI) {
                int m = i & (DI - 1);
                int n = i >> 10;
                float vsum = wm_b[m];
#pragma unroll
                for (int z = 0; z < 8; z++)
                    vsum += g_partW[(size_t)(z * BB + n) * DI + m];
                g_mem[i] = vsum;
                if (s == NSTEP - 1) out[i] = vsum;
            }
        }
        gsync();
    }
}

// ---------------- host ----------------
extern "C" void kernel_launch(void* const* d_in, const int* in_sizes, int n_in,
                              void* d_out, int out_size) {
    const float* ctx      = (const float*)d_in[0];
    const float* question = (const float*)d_in[1];
    const float* kn       = (const float*)d_in[2];
    const float* cinit    = (const float*)d_in[3];
    const float* pa_w     = (const float*)d_in[4];
    const float* pa_b     = (const float*)d_in[5];
    const float* cq_w     = (const float*)d_in[6];
    const float* cq_b     = (const float*)d_in[7];
    const float* ca_w     = (const float*)d_in[8];
    const float* rm_w     = (const float*)d_in[10];
    const float* rm_b     = (const float*)d_in[11];
    const float* ri_w     = (const float*)d_in[12];
    const float* ra_w     = (const float*)d_in[14];
    const float* wm_w     = (const float*)d_in[16];
    const float* wm_b     = (const float*)d_in[17];
    float* out = (float*)d_out;

    mac_persistent<<<NBLK, NTHR>>>(ctx, question, kn, cinit, pa_w, pa_b,
                                   cq_w, cq_b, ca_w, rm_w, rm_b, ri_w,
                                   ra_w, wm_w, wm_b, out);
}

// round 7
// speedup vs baseline: 1.4605x; 1.4605x over previous
#include <cuda_runtime.h>

#define DI 1024
#define D2 2048
#define BB 32
#define SS 128
#define KK 512
#define NSTEP 12
#define NBLK 296
#define NTHR 256

typedef unsigned long long u64;

// ---------------- static device scratch ----------------
__device__ __align__(16) float g_qpa[NSTEP * BB * DI];        // [s][b][d]
__device__ __align__(16) float g_qpaP[4 * BB * NSTEP * DI];   // P0a partials
__device__ __align__(16) float g_cq2P[2 * NSTEP * BB * DI];   // P0c partials
__device__ __align__(16) float g_cq2[NSTEP * BB * DI];        // [s][b][d]
__device__ __align__(16) float g_riwT[D2 * DI];               // riwT[j'][i]
__device__ __align__(16) float g_control[BB * DI];
__device__ __align__(16) float g_mem[BB * DI];
__device__ __align__(16) float g_v[BB * DI];
__device__ __align__(16) float g_read[BB * DI];
__device__ __align__(16) float g_clog[BB * SS];
__device__ __align__(16) float g_rlogP[4 * BB * KK];          // P5 partials over jc
__device__ __align__(16) float g_partA[8 * BB * DI];          // cq partials
__device__ __align__(16) float g_partB[8 * BB * DI];          // mem_p partials
__device__ __align__(16) float g_partU[8 * BB * D2];          // u partials
__device__ __align__(16) float g_partW[16 * BB * DI];         // new_memory partials
__device__ unsigned g_count = 0;
__device__ unsigned g_gen = 0;

// ---------------- grid-wide barrier ----------------
__device__ __forceinline__ void gsync() {
    __syncthreads();
    if (threadIdx.x == 0) {
        __threadfence();
        unsigned gen = *(volatile unsigned*)&g_gen;
        if (atomicAdd(&g_count, 1u) == NBLK - 1) {
            atomicExch(&g_count, 0u);
            __threadfence();
            atomicAdd(&g_gen, 1u);
        } else {
            while (*(volatile unsigned*)&g_gen == gen) __nanosleep(64);
        }
        __threadfence();
    }
    __syncthreads();
}

// ---------------- f32x2 helpers ----------------
__device__ __forceinline__ u64 pk2(float a) {
    u64 r; asm("mov.b64 %0, {%1, %1};" : "=l"(r) : "f"(a)); return r;
}
__device__ __forceinline__ void fma2(u64& c, u64 a, u64 b) {
    asm("fma.rn.f32x2 %0, %1, %2, %0;" : "+l"(c) : "l"(a), "l"(b));
}
__device__ __forceinline__ float2 upk(u64 v) {
    float2 f; asm("mov.b64 {%0, %1}, %2;" : "=f"(f.x), "=f"(f.y) : "l"(v)); return f;
}

// ---------------- 64m x 32n GEMM tile over one k-chunk (f32x2 inner) ----------------
// dst[n*dstride + m0+m] = sum_{k in [kbase,kbase+kchunk)} A[m0+m][k]*act[n][kact+(k-kbase)]
__device__ __forceinline__ void gemm_tile(
    const float* __restrict__ A, int lda, int m0, int kbase, int kchunk,
    const float* __restrict__ act, int ldact, int kact,
    float* __restrict__ dst, int dstride, const float* __restrict__ bias,
    float* __restrict__ pool) {
    float* As = pool;          // [64][65]
    float* Bs = pool + 4160;   // [64][36]
    const int tid = threadIdx.x;
    const int tm = tid & 31;
    const int n0 = (tid >> 5) * 4;
    u64 acc[2][2] = {};
    for (int ks = 0; ks < kchunk; ks += 64) {
#pragma unroll
        for (int i = 0; i < 4; i++) {
            int idx = tid + 256 * i;
            int kg = idx & 15, m = idx >> 4;
            float4 av = *(const float4*)(A + (size_t)(m0 + m) * lda + kbase + ks + kg * 4);
            float* as = As + m * 65 + kg * 4;
            as[0] = av.x; as[1] = av.y; as[2] = av.z; as[3] = av.w;
        }
#pragma unroll
        for (int i = 0; i < 2; i++) {
            int n = (tid & 15) + 16 * i;
            int kg = tid >> 4;
            float4 bv = *(const float4*)(act + (size_t)n * ldact + kact + ks + kg * 4);
            Bs[(kg * 4 + 0) * 36 + n] = bv.x;
            Bs[(kg * 4 + 1) * 36 + n] = bv.y;
            Bs[(kg * 4 + 2) * 36 + n] = bv.z;
            Bs[(kg * 4 + 3) * 36 + n] = bv.w;
        }
        __syncthreads();
#pragma unroll
        for (int k = 0; k < 64; k++) {
            const float* brow = Bs + k * 36 + n0;
            u64 b01 = *(const u64*)(brow);
            u64 b23 = *(const u64*)(brow + 2);
            u64 A0 = pk2(As[tm * 65 + k]);
            u64 A1 = pk2(As[(tm + 32) * 65 + k]);
            fma2(acc[0][0], A0, b01); fma2(acc[0][1], A0, b23);
            fma2(acc[1][0], A1, b01); fma2(acc[1][1], A1, b23);
        }
        __syncthreads();
    }
#pragma unroll
    for (int r = 0; r < 2; r++) {
        int m = m0 + tm + 32 * r;
        float bs = bias ? bias[m] : 0.0f;
        float2 c01 = upk(acc[r][0]);
        float2 c23 = upk(acc[r][1]);
        dst[(size_t)(n0 + 0) * dstride + m] = c01.x + bs;
        dst[(size_t)(n0 + 1) * dstride + m] = c01.y + bs;
        dst[(size_t)(n0 + 2) * dstride + m] = c23.x + bs;
        dst[(size_t)(n0 + 3) * dstride + m] = c23.y + bs;
    }
}

// ---------------- one persistent kernel ----------------
__global__ void __launch_bounds__(NTHR, 2) mac_persistent(
    const float* __restrict__ ctx, const float* __restrict__ question,
    const float* __restrict__ kn, const float* __restrict__ cinit,
    const float* __restrict__ pa_w, const float* __restrict__ pa_b,
    const float* __restrict__ cq_w, const float* __restrict__ cq_b,
    const float* __restrict__ caw, const float* __restrict__ rm_w,
    const float* __restrict__ rm_b, const float* __restrict__ ri_w,
    const float* __restrict__ raw, const float* __restrict__ wm_w,
    const float* __restrict__ wm_b, float* __restrict__ out) {
    __shared__ __align__(16) float pool[6464];  // 25.9 KB
    const int bid = blockIdx.x;
    const int tid = threadIdx.x;

    // ===== P0a: qpa partials (768 tasks) + ri_w transpose + control init =====
    for (int t = bid; t < 768; t += NBLK) {
        int mt = t % 192, z = t / 192;
        gemm_tile(pa_w, D2, mt * 64, z * 512, 512, question, D2, z * 512,
                  g_qpaP + (size_t)z * BB * (NSTEP * DI), NSTEP * DI, nullptr, pool);
    }
    {
        int tx = tid & 31, ty = tid >> 5;
        for (int t = bid; t < 2048; t += NBLK) {
            int jt = t & 63, it = t >> 6;
            int j0 = jt * 32, i0 = it * 32;
            __syncthreads();
#pragma unroll
            for (int r = 0; r < 32; r += 8)
                pool[(ty + r) * 33 + tx] = ri_w[(size_t)(i0 + ty + r) * D2 + j0 + tx];
            __syncthreads();
#pragma unroll
            for (int r = 0; r < 32; r += 8)
                g_riwT[(size_t)(j0 + ty + r) * DI + i0 + tx] = pool[tx * 33 + ty + r];
        }
    }
    for (int i = bid * NTHR + tid; i < BB * DI; i += NBLK * NTHR) g_control[i] = cinit[0];
    gsync();

    // ===== P0b: reduce qpa partials (+bias, scatter, memory0) =====
    for (int idx = bid * NTHR + tid; idx < BB * NSTEP * DI; idx += NBLK * NTHR) {
        int n = idx / (NSTEP * DI);
        int m = idx - n * (NSTEP * DI);
        float v = pa_b[m];
#pragma unroll
        for (int z = 0; z < 4; z++) v += g_qpaP[(size_t)(z * BB + n) * (NSTEP * DI) + m];
        int s0 = m >> 10, d = m & 1023;
        g_qpa[(size_t)(s0 * BB + n) * DI + d] = v;
        if (s0 == 0) g_mem[n * DI + d] = v;
    }
    gsync();

    // ===== P0c: cq2 partials (384 tasks: 12 nb x 16 mt x 2 z) =====
    for (int t = bid; t < 384; t += NBLK) {
        int nb = t % 12, mt = (t / 12) & 15, z = t / 192;
        gemm_tile(cq_w + DI, D2, mt * 64, z * 512, 512,
                  g_qpa + (size_t)nb * BB * DI, DI, z * 512,
                  g_cq2P + (size_t)(z * NSTEP + nb) * BB * DI, DI, nullptr, pool);
    }
    gsync();

    // ===== P0d: reduce cq2 partials + bias =====
    for (int idx = bid * NTHR + tid; idx < NSTEP * BB * DI; idx += NBLK * NTHR) {
        int d = idx & 1023;
        g_cq2[idx] = cq_b[d] + g_cq2P[idx] + g_cq2P[(size_t)NSTEP * BB * DI + idx];
    }
    gsync();

    // ===== 12 recurrent steps =====
    for (int s = 0; s < NSTEP; s++) {
        // ---- P1: cq control-half + mem_p partials (256 tasks) ----
        if (bid < 256) {
            if (bid < 128) {
                int mt = bid & 15, z = bid >> 4;
                gemm_tile(cq_w, D2, mt * 64, z * 128, 128, g_control, DI, z * 128,
                          g_partA + (size_t)z * BB * DI, DI, nullptr, pool);
            } else {
                int q = bid - 128;
                int mt = q & 15, z = q >> 4;
                gemm_tile(rm_w, DI, mt * 64, z * 128, 128, g_mem, DI, z * 128,
                          g_partB + (size_t)z * BB * DI, DI, nullptr, pool);
            }
        }
        gsync();

        // ---- P2: context logits (256 tasks: 32 b x 8 sc) ----
        if (bid < 256) {
            int b = bid >> 3, sc = bid & 7;
            float* w = pool;  // [1024]
            const float* cq2s = g_cq2 + ((size_t)s * BB + b) * DI;
            for (int d = tid; d < DI; d += NTHR) {
                float v = cq2s[d];
#pragma unroll
                for (int z = 0; z < 8; z++) v += g_partA[(size_t)(z * BB + b) * DI + d];
                w[d] = v * caw[d];
            }
            __syncthreads();
            int warp = tid >> 5, lane = tid & 31;
            const float4* w4 = (const float4*)w;
#pragma unroll
            for (int ri = 0; ri < 2; ri++) {
                int srow = sc * 16 + warp * 2 + ri;
                const float4* crow = (const float4*)(ctx + (size_t)(b * SS + srow) * DI);
                float acc = 0.f;
#pragma unroll
                for (int t2 = 0; t2 < 8; t2++) {
                    float4 f = crow[lane + 32 * t2];
                    float4 g = w4[lane + 32 * t2];
                    acc += f.x * g.x + f.y * g.y + f.z * g.z + f.w * g.w;
                }
#pragma unroll
                for (int o = 16; o; o >>= 1) acc += __shfl_xor_sync(0xffffffffu, acc, o);
                if (lane == 0) g_clog[b * SS + srow] = acc;
            }
            __syncthreads();
        }
        gsync();

        // ---- P3: context softmax + weighted sum -> control, v (256 tasks) ----
        if (bid < 256) {
            int b = bid >> 3, dc = bid & 7;
            float* ps = pool;          // [128]
            float* red = pool + 128;   // [128]
            float* comb = pool + 256;  // [128]
            if (tid < SS) { float l = g_clog[b * SS + tid]; ps[tid] = l; red[tid] = l; }
            __syncthreads();
            for (int st = 64; st >= 1; st >>= 1) {
                if (tid < st) red[tid] = fmaxf(red[tid], red[tid + st]);
                __syncthreads();
            }
            float mx = red[0];
            __syncthreads();
            if (tid < SS) { float e = __expf(ps[tid] - mx); ps[tid] = e; red[tid] = e; }
            __syncthreads();
            for (int st = 64; st >= 1; st >>= 1) {
                if (tid < st) red[tid] += red[tid + st];
                __syncthreads();
            }
            float inv = 1.0f / red[0];
            __syncthreads();
            int th = tid & 127, sh = tid >> 7;
            int d = dc * 128 + th;
            const float* base = ctx + (size_t)b * SS * DI + (size_t)sh * 64 * DI + d;
            const float* pw = ps + sh * 64;
            float acc = 0.f;
#pragma unroll 16
            for (int s2 = 0; s2 < 64; s2++) acc += pw[s2] * base[(size_t)s2 * DI];
            if (sh) comb[th] = acc;
            __syncthreads();
            if (!sh) {
                float rv = (acc + comb[th]) * inv;
                g_control[b * DI + d] = rv;
                g_v[b * DI + d] = rv * raw[d];
            }
            __syncthreads();
        }
        gsync();

        // ---- P4: u = v @ riwT^T (256 tasks: 32 mt x 8 z) ----
        if (bid < 256) {
            int mt = bid & 31, z = bid >> 5;
            gemm_tile(g_riwT, DI, mt * 64, z * 128, 128, g_v, DI, z * 128,
                      g_partU + (size_t)z * BB * D2, D2, nullptr, pool);
        }
        gsync();

        // ---- P5: knowledge logits (512 tasks: 32 b x 4 kc x 4 jc) ----
        for (int t = bid; t < 512; t += NBLK) {
            int b = t >> 4, kc = (t >> 2) & 3, jc = t & 3;
            float* w2 = pool;  // [256]
            __syncthreads();
            for (int jj = tid; jj < 256; jj += NTHR) {
                int j = jc * 256 + jj;
                float mp = rm_b[j], u1 = 0.f, u2 = 0.f;
#pragma unroll
                for (int z = 0; z < 8; z++) {
                    mp += g_partB[(size_t)(z * BB + b) * DI + j];
                    u1 += g_partU[(size_t)(z * BB + b) * D2 + j];
                    u2 += g_partU[(size_t)(z * BB + b) * D2 + DI + j];
                }
                w2[jj] = mp * u1 + u2;
            }
            __syncthreads();
            int kq = tid & 31;
            int jw = tid >> 5;
            int k4 = kc * 32 + kq;
            const float4* base = (const float4*)(kn + (size_t)b * DI * KK) + k4;
            float4 acc = {0.f, 0.f, 0.f, 0.f};
#pragma unroll 8
            for (int jj = jw; jj < 256; jj += 8) {
                float wv = w2[jj];
                float4 f = base[(size_t)(jc * 256 + jj) * (KK / 4)];
                acc.x += wv * f.x; acc.y += wv * f.y;
                acc.z += wv * f.z; acc.w += wv * f.w;
            }
            float4* part = (float4*)(pool + 256);  // [8][32]
            part[jw * 32 + kq] = acc;
            __syncthreads();
            if (jw == 0) {
                float4 sm = part[kq];
#pragma unroll
                for (int w = 1; w < 8; w++) {
                    float4 q = part[w * 32 + kq];
                    sm.x += q.x; sm.y += q.y; sm.z += q.z; sm.w += q.w;
                }
                ((float4*)(g_rlogP + ((size_t)jc * BB + b) * KK))[k4] = sm;
            }
            __syncthreads();
        }
        gsync();

        // ---- P6: knowledge softmax + read (512 tasks: 32 b x 16 ic, 64 rows) ----
        for (int t = bid; t < 512; t += NBLK) {
            int b = t >> 4, ic = t & 15;
            float* ps = pool;          // [512]
            float* red = pool + 512;   // [256]
            __syncthreads();
            float v0 = 0.f, v1 = 0.f;
#pragma unroll
            for (int jc = 0; jc < 4; jc++) {
                v0 += g_rlogP[((size_t)jc * BB + b) * KK + tid];
                v1 += g_rlogP[((size_t)jc * BB + b) * KK + 256 + tid];
            }
            red[tid] = fmaxf(v0, v1);
            __syncthreads();
            for (int st = 128; st >= 1; st >>= 1) {
                if (tid < st) red[tid] = fmaxf(red[tid], red[tid + st]);
                __syncthreads();
            }
            float mx = red[0];
            __syncthreads();
            float e0 = __expf(v0 - mx), e1 = __expf(v1 - mx);
            ps[tid] = e0;
            ps[tid + 256] = e1;
            red[tid] = e0 + e1;
            __syncthreads();
            for (int st = 128; st >= 1; st >>= 1) {
                if (tid < st) red[tid] += red[tid + st];
                __syncthreads();
            }
            float inv = 1.0f / red[0];
            __syncthreads();
            int warp = tid >> 5, lane = tid & 31;
            const float4* p4 = (const float4*)ps;
            int i0 = ic * 64 + warp * 8;
#pragma unroll
            for (int rg = 0; rg < 8; rg += 4) {
                const float4* r0 = (const float4*)(kn + (size_t)(b * DI + i0 + rg + 0) * KK);
                const float4* r1 = (const float4*)(kn + (size_t)(b * DI + i0 + rg + 1) * KK);
                const float4* r2 = (const float4*)(kn + (size_t)(b * DI + i0 + rg + 2) * KK);
                const float4* r3 = (const float4*)(kn + (size_t)(b * DI + i0 + rg + 3) * KK);
                float a0 = 0.f, a1 = 0.f, a2 = 0.f, a3 = 0.f;
#pragma unroll
                for (int t2 = 0; t2 < 4; t2++) {
                    float4 q = p4[lane + 32 * t2];
                    float4 f0 = r0[lane + 32 * t2];
                    float4 f1 = r1[lane + 32 * t2];
                    float4 f2 = r2[lane + 32 * t2];
                    float4 f3 = r3[lane + 32 * t2];
                    a0 += f0.x * q.x + f0.y * q.y + f0.z * q.z + f0.w * q.w;
                    a1 += f1.x * q.x + f1.y * q.y + f1.z * q.z + f1.w * q.w;
                    a2 += f2.x * q.x + f2.y * q.y + f2.z * q.z + f2.w * q.w;
                    a3 += f3.x * q.x + f3.y * q.y + f3.z * q.z + f3.w * q.w;
                }
#pragma unroll
                for (int o = 16; o; o >>= 1) {
                    a0 += __shfl_xor_sync(0xffffffffu, a0, o);
                    a1 += __shfl_xor_sync(0xffffffffu, a1, o);
                    a2 += __shfl_xor_sync(0xffffffffu, a2, o);
                    a3 += __shfl_xor_sync(0xffffffffu, a3, o);
                }
                if (lane == 0) {
                    g_read[b * DI + i0 + rg + 0] = a0 * inv;
                    g_read[b * DI + i0 + rg + 1] = a1 * inv;
                    g_read[b * DI + i0 + rg + 2] = a2 * inv;
                    g_read[b * DI + i0 + rg + 3] = a3 * inv;
                }
            }
            __syncthreads();
        }
        gsync();

        // ---- P7: new_memory partials (256 tasks: 16 mt x 16 z) ----
        if (bid < 256) {
            int mt = bid & 15, z = bid >> 4;
            const float* act = (z < 8) ? g_read : g_mem;
            int kact = (z & 7) * 128;
            gemm_tile(wm_w, D2, mt * 64, z * 128, 128, act, DI, kact,
                      g_partW + (size_t)z * BB * DI, DI, nullptr, pool);
        }
        gsync();

        // ---- P8: reduce new_memory partials ----
        {
            int i = bid * NTHR + tid;
            if (i < BB * DI) {
                int m = i & (DI - 1);
                int n = i >> 10;
                float vsum = wm_b[m];
#pragma unroll
                for (int z = 0; z < 16; z++)
                    vsum += g_partW[(size_t)(z * BB + n) * DI + m];
                g_mem[i] = vsum;
                if (s == NSTEP - 1) out[i] = vsum;
            }
        }
        gsync();
    }
}

// ---------------- host ----------------
extern "C" void kernel_launch(void* const* d_in, const int* in_sizes, int n_in,
                              void* d_out, int out_size) {
    const float* ctx      = (const float*)d_in[0];
    const float* question = (const float*)d_in[1];
    const float* kn       = (const float*)d_in[2];
    const float* cinit    = (const float*)d_in[3];
    const float* pa_w     = (const float*)d_in[4];
    const float* pa_b     = (const float*)d_in[5];
    const float* cq_w     = (const float*)d_in[6];
    const float* cq_b     = (const float*)d_in[7];
    const float* ca_w     = (const float*)d_in[8];
    const float* rm_w     = (const float*)d_in[10];
    const float* rm_b     = (const float*)d_in[11];
    const float* ri_w     = (const float*)d_in[12];
    const float* ra_w     = (const float*)d_in[14];
    const float* wm_w     = (const float*)d_in[16];
    const float* wm_b     = (const float*)d_in[17];
    float* out = (float*)d_out;

    mac_persistent<<<NBLK, NTHR>>>(ctx, question, kn, cinit, pa_w, pa_b,
                                   cq_w, cq_b, ca_w, rm_w, rm_b, ri_w,
                                   ra_w, wm_w, wm_b, out);
}

// round 9
// speedup vs baseline: 1.5423x; 1.0560x over previous
#include <cuda_runtime.h>

#define DI 1024
#define D2 2048
#define BB 32
#define SS 128
#define KK 512
#define NSTEP 12
#define NBLK 296
#define NTHR 256

typedef unsigned long long u64;

// ---------------- static device scratch ----------------
__device__ __align__(16) float g_qpa[NSTEP * BB * DI];        // [s][b][d]
__device__ __align__(16) float g_qpaP[4 * BB * NSTEP * DI];   // P0a partials
__device__ __align__(16) float g_cq2P[2 * NSTEP * BB * DI];   // P0c partials
__device__ __align__(16) float g_cq2[NSTEP * BB * DI];        // [s][b][d]
__device__ __align__(16) float g_riwT[D2 * DI];               // riwT[j'][i]
__device__ __align__(16) float g_control[BB * DI];
__device__ __align__(16) float g_mem[BB * DI];
__device__ __align__(16) float g_v[BB * DI];
__device__ __align__(16) float g_read[BB * DI];
__device__ __align__(16) float g_clog[BB * SS];
__device__ __align__(16) float g_rlogP[4 * BB * KK];          // P5 partials over jc
__device__ __align__(16) float g_partA[8 * BB * DI];          // cq partials
__device__ __align__(16) float g_partB[8 * BB * DI];          // mem_p partials
__device__ __align__(16) float g_partU[8 * BB * D2];          // u partials
__device__ __align__(16) float g_partW[16 * BB * DI];         // new_memory partials
__device__ unsigned g_count = 0;
__device__ unsigned g_gen = 0;
__device__ unsigned g_ctr[32];

// ---------------- grid-wide barrier ----------------
__device__ __forceinline__ void gsync() {
    __syncthreads();
    if (threadIdx.x == 0) {
        __threadfence();
        unsigned gen = *(volatile unsigned*)&g_gen;
        if (atomicAdd(&g_count, 1u) == NBLK - 1) {
            atomicExch(&g_count, 0u);
            __threadfence();
            atomicAdd(&g_gen, 1u);
        } else {
            while (*(volatile unsigned*)&g_gen == gen) __nanosleep(64);
        }
        __threadfence();
    }
    __syncthreads();
}

// ---------------- L2 cache policies (createpolicy + cache_hint form) ----------------
__device__ __forceinline__ u64 mkpol_last() {
    u64 p;
    asm("createpolicy.fractional.L2::evict_last.b64 %0, 1.0;" : "=l"(p));
    return p;
}
__device__ __forceinline__ u64 mkpol_first() {
    u64 p;
    asm("createpolicy.fractional.L2::evict_first.b64 %0, 1.0;" : "=l"(p));
    return p;
}
__device__ __forceinline__ float4 ld_pol(const float* p, u64 pol) {
    float4 v;
    asm("ld.global.nc.L2::cache_hint.v4.f32 {%0,%1,%2,%3}, [%4], %5;"
        : "=f"(v.x), "=f"(v.y), "=f"(v.z), "=f"(v.w) : "l"(p), "l"(pol));
    return v;
}

// ---------------- f32x2 helpers ----------------
__device__ __forceinline__ u64 pk2(float a) {
    u64 r; asm("mov.b64 %0, {%1, %1};" : "=l"(r) : "f"(a)); return r;
}
__device__ __forceinline__ void fma2(u64& c, u64 a, u64 b) {
    asm("fma.rn.f32x2 %0, %1, %2, %0;" : "+l"(c) : "l"(a), "l"(b));
}
__device__ __forceinline__ float2 upk(u64 v) {
    float2 f; asm("mov.b64 {%0, %1}, %2;" : "=f"(f.x), "=f"(f.y) : "l"(v)); return f;
}

// ---------------- 64m x 32n GEMM tile (f32x2 inner); APOL 1 = streaming A ----------------
template <int APOL>
__device__ __forceinline__ void gemm_tile(
    const float* __restrict__ A, int lda, int m0, int kbase, int kchunk,
    const float* __restrict__ act, int ldact, int kact,
    float* __restrict__ dst, int dstride, const float* __restrict__ bias,
    float* __restrict__ pool, u64 pol) {
    float* As = pool;          // [64][65]
    float* Bs = pool + 4160;   // [64][36]
    const int tid = threadIdx.x;
    const int tm = tid & 31;
    const int n0 = (tid >> 5) * 4;
    u64 acc[2][2] = {};
    for (int ks = 0; ks < kchunk; ks += 64) {
#pragma unroll
        for (int i = 0; i < 4; i++) {
            int idx = tid + 256 * i;
            int kg = idx & 15, m = idx >> 4;
            const float* ap = A + (size_t)(m0 + m) * lda + kbase + ks + kg * 4;
            float4 av = APOL ? ld_pol(ap, pol) : *(const float4*)ap;
            float* as = As + m * 65 + kg * 4;
            as[0] = av.x; as[1] = av.y; as[2] = av.z; as[3] = av.w;
        }
#pragma unroll
        for (int i = 0; i < 2; i++) {
            int n = (tid & 15) + 16 * i;
            int kg = tid >> 4;
            float4 bv = *(const float4*)(act + (size_t)n * ldact + kact + ks + kg * 4);
            Bs[(kg * 4 + 0) * 36 + n] = bv.x;
            Bs[(kg * 4 + 1) * 36 + n] = bv.y;
            Bs[(kg * 4 + 2) * 36 + n] = bv.z;
            Bs[(kg * 4 + 3) * 36 + n] = bv.w;
        }
        __syncthreads();
#pragma unroll
        for (int k = 0; k < 64; k++) {
            const float* brow = Bs + k * 36 + n0;
            u64 b01 = *(const u64*)(brow);
            u64 b23 = *(const u64*)(brow + 2);
            u64 A0 = pk2(As[tm * 65 + k]);
            u64 A1 = pk2(As[(tm + 32) * 65 + k]);
            fma2(acc[0][0], A0, b01); fma2(acc[0][1], A0, b23);
            fma2(acc[1][0], A1, b01); fma2(acc[1][1], A1, b23);
        }
        __syncthreads();
    }
#pragma unroll
    for (int r = 0; r < 2; r++) {
        int m = m0 + tm + 32 * r;
        float bs = bias ? bias[m] : 0.0f;
        float2 c01 = upk(acc[r][0]);
        float2 c23 = upk(acc[r][1]);
        dst[(size_t)(n0 + 0) * dstride + m] = c01.x + bs;
        dst[(size_t)(n0 + 1) * dstride + m] = c01.y + bs;
        dst[(size_t)(n0 + 2) * dstride + m] = c23.x + bs;
        dst[(size_t)(n0 + 3) * dstride + m] = c23.y + bs;
    }
}

// ---------------- work-steal helper ----------------
__device__ __forceinline__ int steal(int ph, int ntasks, int* s_task) {
    __syncthreads();
    if (threadIdx.x == 0) *s_task = (int)atomicAdd(&g_ctr[ph], 1u);
    __syncthreads();
    int t = *s_task;
    return (t < ntasks) ? t : -1;
}

__global__ void reset_ctrs() {
    if (threadIdx.x < 32) g_ctr[threadIdx.x] = 0;
}

// ---------------- one persistent kernel ----------------
__global__ void __launch_bounds__(NTHR, 2) mac_persistent(
    const float* __restrict__ ctx, const float* __restrict__ question,
    const float* __restrict__ kn, const float* __restrict__ cinit,
    const float* __restrict__ pa_w, const float* __restrict__ pa_b,
    const float* __restrict__ cq_w, const float* __restrict__ cq_b,
    const float* __restrict__ caw, const float* __restrict__ rm_w,
    const float* __restrict__ rm_b, const float* __restrict__ ri_w,
    const float* __restrict__ raw, const float* __restrict__ wm_w,
    const float* __restrict__ wm_b, float* __restrict__ out) {
    __shared__ __align__(16) float pool[6464];  // 25.9 KB
    __shared__ int s_task;
    const int bid = blockIdx.x;
    const int tid = threadIdx.x;
    const u64 PPIN = mkpol_last();
    const u64 PSTR = mkpol_first();

    // ===== P0a: qpa partials (768 tasks, stolen) + transpose (2048, stolen) + init =====
    for (int t; (t = steal(0, 768, &s_task)) >= 0;) {
        int mt = t % 192, z = t / 192;
        gemm_tile<1>(pa_w, D2, mt * 64, z * 512, 512, question, D2, z * 512,
                     g_qpaP + (size_t)z * BB * (NSTEP * DI), NSTEP * DI, nullptr, pool, PSTR);
    }
    {
        int tx = tid & 31, ty = tid >> 5;
        for (int t; (t = steal(1, 2048, &s_task)) >= 0;) {
            int jt = t & 63, it = t >> 6;
            int j0 = jt * 32, i0 = it * 32;
            __syncthreads();
#pragma unroll
            for (int r = 0; r < 32; r += 8)
                pool[(ty + r) * 33 + tx] = ri_w[(size_t)(i0 + ty + r) * D2 + j0 + tx];
            __syncthreads();
#pragma unroll
            for (int r = 0; r < 32; r += 8)
                g_riwT[(size_t)(j0 + ty + r) * DI + i0 + tx] = pool[tx * 33 + ty + r];
        }
    }
    for (int i = bid * NTHR + tid; i < BB * DI; i += NBLK * NTHR) g_control[i] = cinit[0];
    gsync();

    // ===== P0b: reduce qpa partials (+bias, scatter, memory0) =====
    for (int idx = bid * NTHR + tid; idx < BB * NSTEP * DI; idx += NBLK * NTHR) {
        int n = idx / (NSTEP * DI);
        int m = idx - n * (NSTEP * DI);
        float v = pa_b[m];
#pragma unroll
        for (int z = 0; z < 4; z++) v += g_qpaP[(size_t)(z * BB + n) * (NSTEP * DI) + m];
        int s0 = m >> 10, d = m & 1023;
        g_qpa[(size_t)(s0 * BB + n) * DI + d] = v;
        if (s0 == 0) g_mem[n * DI + d] = v;
    }
    gsync();

    // ===== P0c: cq2 partials (384 tasks, stolen) =====
    for (int t; (t = steal(2, 384, &s_task)) >= 0;) {
        int nb = t % 12, mt = (t / 12) & 15, z = t / 192;
        gemm_tile<1>(cq_w + DI, D2, mt * 64, z * 512, 512,
                     g_qpa + (size_t)nb * BB * DI, DI, z * 512,
                     g_cq2P + (size_t)(z * NSTEP + nb) * BB * DI, DI, nullptr, pool, PSTR);
    }
    gsync();

    // ===== P0d: reduce cq2 partials + bias =====
    for (int idx = bid * NTHR + tid; idx < NSTEP * BB * DI; idx += NBLK * NTHR) {
        int d = idx & 1023;
        g_cq2[idx] = cq_b[d] + g_cq2P[idx] + g_cq2P[(size_t)NSTEP * BB * DI + idx];
    }
    gsync();

    // ===== 12 recurrent steps =====
    for (int s = 0; s < NSTEP; s++) {
        // ---- P1: cq control-half + mem_p partials (256 tasks) ----
        if (bid < 256) {
            if (bid < 128) {
                int mt = bid & 15, z = bid >> 4;
                gemm_tile<1>(cq_w, D2, mt * 64, z * 128, 128, g_control, DI, z * 128,
                             g_partA + (size_t)z * BB * DI, DI, nullptr, pool, PSTR);
            } else {
                int q = bid - 128;
                int mt = q & 15, z = q >> 4;
                gemm_tile<1>(rm_w, DI, mt * 64, z * 128, 128, g_mem, DI, z * 128,
                             g_partB + (size_t)z * BB * DI, DI, nullptr, pool, PSTR);
            }
        }
        gsync();

        // ---- P2: context logits (256 tasks: 32 b x 8 sc) ----
        if (bid < 256) {
            int b = bid >> 3, sc = bid & 7;
            float* w = pool;  // [1024]
            const float* cq2s = g_cq2 + ((size_t)s * BB + b) * DI;
            for (int d = tid; d < DI; d += NTHR) {
                float v = cq2s[d];
#pragma unroll
                for (int z = 0; z < 8; z++) v += g_partA[(size_t)(z * BB + b) * DI + d];
                w[d] = v * caw[d];
            }
            __syncthreads();
            int warp = tid >> 5, lane = tid & 31;
            const float4* w4 = (const float4*)w;
#pragma unroll
            for (int ri = 0; ri < 2; ri++) {
                int srow = sc * 16 + warp * 2 + ri;
                const float* crow = ctx + (size_t)(b * SS + srow) * DI;
                float acc = 0.f;
#pragma unroll
                for (int t2 = 0; t2 < 8; t2++) {
                    float4 f = ld_pol(crow + (lane + 32 * t2) * 4, PPIN);
                    float4 g = w4[lane + 32 * t2];
                    acc += f.x * g.x + f.y * g.y + f.z * g.z + f.w * g.w;
                }
#pragma unroll
                for (int o = 16; o; o >>= 1) acc += __shfl_xor_sync(0xffffffffu, acc, o);
                if (lane == 0) g_clog[b * SS + srow] = acc;
            }
            __syncthreads();
        }
        gsync();

        // ---- P3: context softmax + weighted sum -> control, v (256 tasks) ----
        if (bid < 256) {
            int b = bid >> 3, dc = bid & 7;
            float* ps = pool;          // [128]
            float* red = pool + 128;   // [128]
            float* comb = pool + 256;  // [128]
            if (tid < SS) { float l = g_clog[b * SS + tid]; ps[tid] = l; red[tid] = l; }
            __syncthreads();
            for (int st = 64; st >= 1; st >>= 1) {
                if (tid < st) red[tid] = fmaxf(red[tid], red[tid + st]);
                __syncthreads();
            }
            float mx = red[0];
            __syncthreads();
            if (tid < SS) { float e = __expf(ps[tid] - mx); ps[tid] = e; red[tid] = e; }
            __syncthreads();
            for (int st = 64; st >= 1; st >>= 1) {
                if (tid < st) red[tid] += red[tid + st];
                __syncthreads();
            }
            float inv = 1.0f / red[0];
            __syncthreads();
            int th = tid & 127, sh = tid >> 7;
            int d = dc * 128 + th;
            const float* base = ctx + (size_t)b * SS * DI + (size_t)sh * 64 * DI + d;
            const float* pw = ps + sh * 64;
            float acc = 0.f;
#pragma unroll 16
            for (int s2 = 0; s2 < 64; s2++) acc += pw[s2] * base[(size_t)s2 * DI];
            if (sh) comb[th] = acc;
            __syncthreads();
            if (!sh) {
                float rv = (acc + comb[th]) * inv;
                g_control[b * DI + d] = rv;
                g_v[b * DI + d] = rv * raw[d];
            }
            __syncthreads();
        }
        gsync();

        // ---- P4: u = v @ riwT^T (256 tasks: 32 mt x 8 z) ----
        if (bid < 256) {
            int mt = bid & 31, z = bid >> 5;
            gemm_tile<0>(g_riwT, DI, mt * 64, z * 128, 128, g_v, DI, z * 128,
                         g_partU + (size_t)z * BB * D2, D2, nullptr, pool, PSTR);
        }
        gsync();

        // ---- P5: knowledge logits (512 tasks, stolen) ----
        for (int t; (t = steal(3 + s * 2, 512, &s_task)) >= 0;) {
            int b = t >> 4, kc = (t >> 2) & 3, jc = t & 3;
            float* w2 = pool;  // [256]
            __syncthreads();
            for (int jj = tid; jj < 256; jj += NTHR) {
                int j = jc * 256 + jj;
                float mp = rm_b[j], u1 = 0.f, u2 = 0.f;
#pragma unroll
                for (int z = 0; z < 8; z++) {
                    mp += g_partB[(size_t)(z * BB + b) * DI + j];
                    u1 += g_partU[(size_t)(z * BB + b) * D2 + j];
                    u2 += g_partU[(size_t)(z * BB + b) * D2 + DI + j];
                }
                w2[jj] = mp * u1 + u2;
            }
            __syncthreads();
            int kq = tid & 31;
            int jw = tid >> 5;
            int k4 = kc * 32 + kq;
            const float* base = kn + (size_t)b * DI * KK + k4 * 4;
            float4 acc = {0.f, 0.f, 0.f, 0.f};
#pragma unroll 8
            for (int jj = jw; jj < 256; jj += 8) {
                float wv = w2[jj];
                float4 f = ld_pol(base + (size_t)(jc * 256 + jj) * KK, PPIN);
                acc.x += wv * f.x; acc.y += wv * f.y;
                acc.z += wv * f.z; acc.w += wv * f.w;
            }
            float4* part = (float4*)(pool + 256);  // [8][32]
            part[jw * 32 + kq] = acc;
            __syncthreads();
            if (jw == 0) {
                float4 sm = part[kq];
#pragma unroll
                for (int w = 1; w < 8; w++) {
                    float4 q = part[w * 32 + kq];
                    sm.x += q.x; sm.y += q.y; sm.z += q.z; sm.w += q.w;
                }
                ((float4*)(g_rlogP + ((size_t)jc * BB + b) * KK))[k4] = sm;
            }
            __syncthreads();
        }
        gsync();

        // ---- P6: knowledge softmax + read (512 tasks, stolen) ----
        for (int t; (t = steal(4 + s * 2, 512, &s_task)) >= 0;) {
            int b = t >> 4, ic = t & 15;
            float* ps = pool;          // [512]
            float* red = pool + 512;   // [256]
            __syncthreads();
            float v0 = 0.f, v1 = 0.f;
#pragma unroll
            for (int jc = 0; jc < 4; jc++) {
                v0 += g_rlogP[((size_t)jc * BB + b) * KK + tid];
                v1 += g_rlogP[((size_t)jc * BB + b) * KK + 256 + tid];
            }
            red[tid] = fmaxf(v0, v1);
            __syncthreads();
            for (int st = 128; st >= 1; st >>= 1) {
                if (tid < st) red[tid] = fmaxf(red[tid], red[tid + st]);
                __syncthreads();
            }
            float mx = red[0];
            __syncthreads();
            float e0 = __expf(v0 - mx), e1 = __expf(v1 - mx);
            ps[tid] = e0;
            ps[tid + 256] = e1;
            red[tid] = e0 + e1;
            __syncthreads();
            for (int st = 128; st >= 1; st >>= 1) {
                if (tid < st) red[tid] += red[tid + st];
                __syncthreads();
            }
            float inv = 1.0f / red[0];
            __syncthreads();
            int warp = tid >> 5, lane = tid & 31;
            const float4* p4 = (const float4*)ps;
            int i0 = ic * 64 + warp * 8;
#pragma unroll
            for (int rg = 0; rg < 8; rg += 4) {
                const float* r0 = kn + (size_t)(b * DI + i0 + rg + 0) * KK;
                const float* r1 = kn + (size_t)(b * DI + i0 + rg + 1) * KK;
                const float* r2 = kn + (size_t)(b * DI + i0 + rg + 2) * KK;
                const float* r3 = kn + (size_t)(b * DI + i0 + rg + 3) * KK;
                float a0 = 0.f, a1 = 0.f, a2 = 0.f, a3 = 0.f;
#pragma unroll
                for (int t2 = 0; t2 < 4; t2++) {
                    int off = (lane + 32 * t2) * 4;
                    float4 q = p4[lane + 32 * t2];
                    float4 f0 = ld_pol(r0 + off, PPIN);
                    float4 f1 = ld_pol(r1 + off, PPIN);
                    float4 f2 = ld_pol(r2 + off, PPIN);
                    float4 f3 = ld_pol(r3 + off, PPIN);
                    a0 += f0.x * q.x + f0.y * q.y + f0.z * q.z + f0.w * q.w;
                    a1 += f1.x * q.x + f1.y * q.y + f1.z * q.z + f1.w * q.w;
                    a2 += f2.x * q.x + f2.y * q.y + f2.z * q.z + f2.w * q.w;
                    a3 += f3.x * q.x + f3.y * q.y + f3.z * q.z + f3.w * q.w;
                }
#pragma unroll
                for (int o = 16; o; o >>= 1) {
                    a0 += __shfl_xor_sync(0xffffffffu, a0, o);
                    a1 += __shfl_xor_sync(0xffffffffu, a1, o);
                    a2 += __shfl_xor_sync(0xffffffffu, a2, o);
                    a3 += __shfl_xor_sync(0xffffffffu, a3, o);
                }
                if (lane == 0) {
                    g_read[b * DI + i0 + rg + 0] = a0 * inv;
                    g_read[b * DI + i0 + rg + 1] = a1 * inv;
                    g_read[b * DI + i0 + rg + 2] = a2 * inv;
                    g_read[b * DI + i0 + rg + 3] = a3 * inv;
                }
            }
            __syncthreads();
        }
        gsync();

        // ---- P7: new_memory partials (256 tasks: 16 mt x 16 z) ----
        if (bid < 256) {
            int mt = bid & 15, z = bid >> 4;
            const float* act = (z < 8) ? g_read : g_mem;
            int kact = (z & 7) * 128;
            gemm_tile<1>(wm_w, D2, mt * 64, z * 128, 128, act, DI, kact,
                         g_partW + (size_t)z * BB * DI, DI, nullptr, pool, PSTR);
        }
        gsync();

        // ---- P8: reduce new_memory partials ----
        {
            int i = bid * NTHR + tid;
            if (i < BB * DI) {
                int m = i & (DI - 1);
                int n = i >> 10;
                float vsum = wm_b[m];
#pragma unroll
                for (int z = 0; z < 16; z++)
                    vsum += g_partW[(size_t)(z * BB + n) * DI + m];
                g_mem[i] = vsum;
                if (s == NSTEP - 1) out[i] = vsum;
            }
        }
        gsync();
    }
}

// ---------------- host ----------------
extern "C" void kernel_launch(void* const* d_in, const int* in_sizes, int n_in,
                              void* d_out, int out_size) {
    const float* ctx      = (const float*)d_in[0];
    const float* question = (const float*)d_in[1];
    const float* kn       = (const float*)d_in[2];
    const float* cinit    = (const float*)d_in[3];
    const float* pa_w     = (const float*)d_in[4];
    const float* pa_b     = (const float*)d_in[5];
    const float* cq_w     = (const float*)d_in[6];
    const float* cq_b     = (const float*)d_in[7];
    const float* ca_w     = (const float*)d_in[8];
    const float* rm_w     = (const float*)d_in[10];
    const float* rm_b     = (const float*)d_in[11];
    const float* ri_w     = (const float*)d_in[12];
    const float* ra_w     = (const float*)d_in[14];
    const float* wm_w     = (const float*)d_in[16];
    const float* wm_b     = (const float*)d_in[17];
    float* out = (float*)d_out;

    reset_ctrs<<<1, 32>>>();
    mac_persistent<<<NBLK, NTHR>>>(ctx, question, kn, cinit, pa_w, pa_b,
                                   cq_w, cq_b, ca_w, rm_w, rm_b, ri_w,
                                   ra_w, wm_w, wm_b, out);
}